// round 3
// baseline (speedup 1.0000x reference)
#include <cuda_runtime.h>
#include <math.h>
#include <stdint.h>

// ============================================================
// ReliabilityGatedCrossAttention  (B=4, N=1024, DIM=1024, H=16, d=64)
//   q = Xq @ Wq^T + bq ; k = (Xkv @ Wk^T + bk) * r ; v = (Xkv @ Wv^T + bv) * r
//   S = q k^T * d^-0.5 + log(clip(r,1e-6)) ; P = softmax(S) ; O = P v
//   out = O @ Wo^T + bo
// All matmuls via mma.sync.m16n8k8 tf32 (fp32 accumulate).
// ============================================================

#define DIMC   1024
#define HEADS  16
#define HDIM   64
#define BATCH  4
#define NQL    1024
#define NKVL   1024
#define MROWS  (BATCH * NQL)   // 4096

// -------- scratch (no allocations allowed) --------
__device__ float g_q [(size_t)MROWS * DIMC];
__device__ float g_k [(size_t)MROWS * DIMC];
__device__ float g_v [(size_t)MROWS * DIMC];
__device__ float g_ao[(size_t)MROWS * DIMC];

// -------- helpers --------
__device__ __forceinline__ float f2tf32(float x) {
    uint32_t u;
    asm("cvt.rna.tf32.f32 %0, %1;" : "=r"(u) : "f"(x));
    return __uint_as_float(u);
}

__device__ __forceinline__ void mma_tf32(float c[4], const uint32_t a[4], const uint32_t b[2]) {
    asm volatile(
        "mma.sync.aligned.m16n8k8.row.col.f32.tf32.tf32.f32 "
        "{%0,%1,%2,%3},{%4,%5,%6,%7},{%8,%9},{%0,%1,%2,%3};\n"
        : "+f"(c[0]), "+f"(c[1]), "+f"(c[2]), "+f"(c[3])
        : "r"(a[0]), "r"(a[1]), "r"(a[2]), "r"(a[3]), "r"(b[0]), "r"(b[1]));
}

// ============================================================
// GEMM-NT:  C[m,n] = (sum_k A[m,k] * W[n,k] + bias[n]) * (GATE ? gate[m] : 1)
// A: MxK row-major, W: NxK row-major.  BM=BN=128, BK=32, 256 threads.
// smem stride 36 (== 4 mod 32) -> conflict-free fragment LDS.
// ============================================================
#define BM 128
#define BN 128
#define BK 32
#define SAo 36   // padded smem row stride (floats)

template<bool GATE>
__global__ __launch_bounds__(256)
void gemm_nt(const float* __restrict__ A, const float* __restrict__ W,
             const float* __restrict__ bias, const float* __restrict__ gate,
             float* __restrict__ C, int M, int N, int K)
{
    extern __shared__ float sm[];
    float* As = sm;                       // [2][BM][SAo]
    float* Bs = sm + 2 * BM * SAo;        // [2][BN][SAo]

    const int tid  = threadIdx.x;
    const int wid  = tid >> 5;
    const int lane = tid & 31;
    const int g    = lane >> 2;           // group id (row within frag)
    const int t    = lane & 3;            // thread-in-group
    const int m0 = blockIdx.y * BM;
    const int n0 = blockIdx.x * BN;
    const int wm = (wid >> 2) * 64;       // warp m-offset (2 warps in M)
    const int wn = (wid & 3) * 32;        // warp n-offset (4 warps in N)

    const int lr = tid >> 3;              // 0..31 (tile row)
    const int lc = (tid & 7) * 4;         // 0..28 (tile col, float4)

    float acc[4][4][4];
    #pragma unroll
    for (int i = 0; i < 4; i++)
        #pragma unroll
        for (int j = 0; j < 4; j++)
            #pragma unroll
            for (int c = 0; c < 4; c++) acc[i][j][c] = 0.f;

    const float* Ag = A + (size_t)(m0 + lr) * K + lc;
    const float* Bg = W + (size_t)(n0 + lr) * K + lc;

    float4 ra[4], rb[4];
    #pragma unroll
    for (int i = 0; i < 4; i++) {
        ra[i] = *(const float4*)(Ag + (size_t)(32 * i) * K);
        rb[i] = *(const float4*)(Bg + (size_t)(32 * i) * K);
    }
    #pragma unroll
    for (int i = 0; i < 4; i++) {
        float4 a = ra[i];
        a.x = f2tf32(a.x); a.y = f2tf32(a.y); a.z = f2tf32(a.z); a.w = f2tf32(a.w);
        *(float4*)(As + (lr + 32 * i) * SAo + lc) = a;
        float4 bt = rb[i];
        bt.x = f2tf32(bt.x); bt.y = f2tf32(bt.y); bt.z = f2tf32(bt.z); bt.w = f2tf32(bt.w);
        *(float4*)(Bs + (lr + 32 * i) * SAo + lc) = bt;
    }

    int buf = 0;
    const int KT = K / BK;
    for (int kt = 0; kt < KT; kt++) {
        __syncthreads();
        const bool more = (kt + 1 < KT);
        if (more) {
            const float* Ag2 = Ag + (kt + 1) * BK;
            const float* Bg2 = Bg + (kt + 1) * BK;
            #pragma unroll
            for (int i = 0; i < 4; i++) {
                ra[i] = *(const float4*)(Ag2 + (size_t)(32 * i) * K);
                rb[i] = *(const float4*)(Bg2 + (size_t)(32 * i) * K);
            }
        }
        const float* Ab = As + buf * BM * SAo + wm * SAo;
        const float* Bb = Bs + buf * BN * SAo + wn * SAo;
        #pragma unroll
        for (int ks = 0; ks < 4; ks++) {
            const int kk = ks * 8;
            uint32_t af[4][4];
            #pragma unroll
            for (int mi = 0; mi < 4; mi++) {
                const float* p = Ab + (mi * 16 + g) * SAo + kk + t;
                af[mi][0] = __float_as_uint(p[0]);
                af[mi][1] = __float_as_uint(p[8 * SAo]);
                af[mi][2] = __float_as_uint(p[4]);
                af[mi][3] = __float_as_uint(p[8 * SAo + 4]);
            }
            uint32_t bf[4][2];
            #pragma unroll
            for (int ni = 0; ni < 4; ni++) {
                const float* p = Bb + (ni * 8 + g) * SAo + kk + t;
                bf[ni][0] = __float_as_uint(p[0]);
                bf[ni][1] = __float_as_uint(p[4]);
            }
            #pragma unroll
            for (int mi = 0; mi < 4; mi++)
                #pragma unroll
                for (int ni = 0; ni < 4; ni++)
                    mma_tf32(acc[mi][ni], af[mi], bf[ni]);
        }
        if (more) {
            float* Ad = As + (buf ^ 1) * BM * SAo;
            float* Bd = Bs + (buf ^ 1) * BN * SAo;
            #pragma unroll
            for (int i = 0; i < 4; i++) {
                float4 a = ra[i];
                a.x = f2tf32(a.x); a.y = f2tf32(a.y); a.z = f2tf32(a.z); a.w = f2tf32(a.w);
                *(float4*)(Ad + (lr + 32 * i) * SAo + lc) = a;
                float4 bt = rb[i];
                bt.x = f2tf32(bt.x); bt.y = f2tf32(bt.y); bt.z = f2tf32(bt.z); bt.w = f2tf32(bt.w);
                *(float4*)(Bd + (lr + 32 * i) * SAo + lc) = bt;
            }
        }
        buf ^= 1;
    }

    // epilogue
    #pragma unroll
    for (int ni = 0; ni < 4; ni++) {
        const int cc = n0 + wn + ni * 8 + 2 * t;
        const float b0 = bias[cc];
        const float b1 = bias[cc + 1];
        #pragma unroll
        for (int mi = 0; mi < 4; mi++) {
            const int rr = m0 + wm + mi * 16 + g;
            float v0 = acc[mi][ni][0] + b0;
            float v1 = acc[mi][ni][1] + b1;
            float v2 = acc[mi][ni][2] + b0;
            float v3 = acc[mi][ni][3] + b1;
            if (GATE) {
                const float g0 = gate[rr];
                const float g1 = gate[rr + 8];
                v0 *= g0; v1 *= g0; v2 *= g1; v3 *= g1;
            }
            *(float2*)(C + (size_t)rr * N + cc)       = make_float2(v0, v1);
            *(float2*)(C + (size_t)(rr + 8) * N + cc) = make_float2(v2, v3);
        }
    }
}

// ============================================================
// Flash attention per (b, h, 128-query tile).  KV tiles of 64.
// 8 warps, each owns 16 query rows.  Online softmax with log(r) bias.
// ============================================================
#define SQ 68   // smem row stride (== 4 mod 32 -> conflict-free frags)

__global__ __launch_bounds__(256)
void flash_attn(const float* __restrict__ Q, const float* __restrict__ Kg,
                const float* __restrict__ V, const float* __restrict__ rel,
                float* __restrict__ O)
{
    extern __shared__ float sm[];
    float* Qs  = sm;                 // [128][SQ]
    float* Ks  = Qs + 128 * SQ;      // [64][SQ]   K tile, row-major [kv][d]
    float* Vt  = Ks + 64 * SQ;       // [64][SQ]   V tile transposed [d][kv]
    float* Ps  = Vt + 64 * SQ;       // [128][SQ]  P (exp scores), tf32
    float* slr = Ps + 128 * SQ;      // [64]       log reliability

    const int tid  = threadIdx.x;
    const int wid  = tid >> 5;
    const int lane = tid & 31;
    const int g    = lane >> 2;
    const int t    = lane & 3;
    const int q0   = blockIdx.x * 128;
    const int h    = blockIdx.y;
    const int b    = blockIdx.z;
    const int col0 = h * HDIM;
    const int wq   = wid * 16;

    // load Q tile (persistent)
    {
        const int r  = tid >> 4;
        const int c4 = (tid & 15) * 4;
        #pragma unroll
        for (int i = 0; i < 8; i++) {
            const int rr = r + 16 * i;
            float4 v = *(const float4*)(Q + (size_t)(b * NQL + q0 + rr) * DIMC + col0 + c4);
            v.x = f2tf32(v.x); v.y = f2tf32(v.y); v.z = f2tf32(v.z); v.w = f2tf32(v.w);
            *(float4*)(Qs + rr * SQ + c4) = v;
        }
    }

    float mrow[2] = {-1e30f, -1e30f};
    float lrow[2] = {0.f, 0.f};
    float oacc[8][4];
    #pragma unroll
    for (int i = 0; i < 8; i++)
        #pragma unroll
        for (int c = 0; c < 4; c++) oacc[i][c] = 0.f;

    for (int kt = 0; kt < NKVL; kt += 64) {
        __syncthreads();   // previous tile fully consumed
        {
            const int r  = tid >> 4;
            const int c4 = (tid & 15) * 4;
            #pragma unroll
            for (int i = 0; i < 4; i++) {
                const int rr = r + 16 * i;
                const size_t go = (size_t)(b * NKVL + kt + rr) * DIMC + col0 + c4;
                float4 kv = *(const float4*)(Kg + go);
                kv.x = f2tf32(kv.x); kv.y = f2tf32(kv.y); kv.z = f2tf32(kv.z); kv.w = f2tf32(kv.w);
                *(float4*)(Ks + rr * SQ + c4) = kv;
                float4 vv = *(const float4*)(V + go);
                Vt[(c4 + 0) * SQ + rr] = f2tf32(vv.x);
                Vt[(c4 + 1) * SQ + rr] = f2tf32(vv.y);
                Vt[(c4 + 2) * SQ + rr] = f2tf32(vv.z);
                Vt[(c4 + 3) * SQ + rr] = f2tf32(vv.w);
            }
            if (tid < 64) {
                const float rv = rel[b * NKVL + kt + tid];
                slr[tid] = logf(fmaxf(rv, 1e-6f));
            }
        }
        __syncthreads();

        // S = Q K^T (16x64 per warp)
        float sacc[8][4];
        #pragma unroll
        for (int i = 0; i < 8; i++)
            #pragma unroll
            for (int c = 0; c < 4; c++) sacc[i][c] = 0.f;
        #pragma unroll
        for (int ks = 0; ks < 8; ks++) {
            const int kk = ks * 8;
            uint32_t af[4];
            const float* ap = Qs + (wq + g) * SQ + kk + t;
            af[0] = __float_as_uint(ap[0]);
            af[1] = __float_as_uint(ap[8 * SQ]);
            af[2] = __float_as_uint(ap[4]);
            af[3] = __float_as_uint(ap[8 * SQ + 4]);
            #pragma unroll
            for (int ni = 0; ni < 8; ni++) {
                uint32_t bf[2];
                const float* bp = Ks + (ni * 8 + g) * SQ + kk + t;
                bf[0] = __float_as_uint(bp[0]);
                bf[1] = __float_as_uint(bp[4]);
                mma_tf32(sacc[ni], af, bf);
            }
        }

        // softmax: scale, +log(r), running max / sum
        float mt0 = -1e30f, mt1 = -1e30f;
        #pragma unroll
        for (int ni = 0; ni < 8; ni++) {
            const int c = ni * 8 + 2 * t;
            const float l0 = slr[c], l1 = slr[c + 1];
            sacc[ni][0] = sacc[ni][0] * 0.125f + l0;
            sacc[ni][1] = sacc[ni][1] * 0.125f + l1;
            sacc[ni][2] = sacc[ni][2] * 0.125f + l0;
            sacc[ni][3] = sacc[ni][3] * 0.125f + l1;
            mt0 = fmaxf(mt0, fmaxf(sacc[ni][0], sacc[ni][1]));
            mt1 = fmaxf(mt1, fmaxf(sacc[ni][2], sacc[ni][3]));
        }
        mt0 = fmaxf(mt0, __shfl_xor_sync(0xffffffffu, mt0, 1));
        mt0 = fmaxf(mt0, __shfl_xor_sync(0xffffffffu, mt0, 2));
        mt1 = fmaxf(mt1, __shfl_xor_sync(0xffffffffu, mt1, 1));
        mt1 = fmaxf(mt1, __shfl_xor_sync(0xffffffffu, mt1, 2));
        const float mn0 = fmaxf(mrow[0], mt0);
        const float mn1 = fmaxf(mrow[1], mt1);

        float rs0 = 0.f, rs1 = 0.f;
        #pragma unroll
        for (int ni = 0; ni < 8; ni++) {
            const float p0 = __expf(sacc[ni][0] - mn0);
            const float p1 = __expf(sacc[ni][1] - mn0);
            const float p2 = __expf(sacc[ni][2] - mn1);
            const float p3 = __expf(sacc[ni][3] - mn1);
            rs0 += p0 + p1;
            rs1 += p2 + p3;
            const int c = ni * 8 + 2 * t;
            *(float2*)(Ps + (wq + g) * SQ + c)       = make_float2(f2tf32(p0), f2tf32(p1));
            *(float2*)(Ps + (wq + g + 8) * SQ + c)   = make_float2(f2tf32(p2), f2tf32(p3));
        }
        rs0 += __shfl_xor_sync(0xffffffffu, rs0, 1);
        rs0 += __shfl_xor_sync(0xffffffffu, rs0, 2);
        rs1 += __shfl_xor_sync(0xffffffffu, rs1, 1);
        rs1 += __shfl_xor_sync(0xffffffffu, rs1, 2);

        const float al0 = __expf(mrow[0] - mn0);
        const float al1 = __expf(mrow[1] - mn1);
        lrow[0] = lrow[0] * al0 + rs0;
        lrow[1] = lrow[1] * al1 + rs1;
        mrow[0] = mn0; mrow[1] = mn1;
        #pragma unroll
        for (int ni = 0; ni < 8; ni++) {
            oacc[ni][0] *= al0; oacc[ni][1] *= al0;
            oacc[ni][2] *= al1; oacc[ni][3] *= al1;
        }
        __syncwarp();   // Ps visible within warp

        // O += P V  (A = Ps rows of this warp, B = Vt)
        #pragma unroll
        for (int ks = 0; ks < 8; ks++) {
            const int kk = ks * 8;
            uint32_t af[4];
            const float* ap = Ps + (wq + g) * SQ + kk + t;
            af[0] = __float_as_uint(ap[0]);
            af[1] = __float_as_uint(ap[8 * SQ]);
            af[2] = __float_as_uint(ap[4]);
            af[3] = __float_as_uint(ap[8 * SQ + 4]);
            #pragma unroll
            for (int ni = 0; ni < 8; ni++) {
                uint32_t bf[2];
                const float* bp = Vt + (ni * 8 + g) * SQ + kk + t;
                bf[0] = __float_as_uint(bp[0]);
                bf[1] = __float_as_uint(bp[4]);
                mma_tf32(oacc[ni], af, bf);
            }
        }
    }

    const float il0 = 1.f / lrow[0];
    const float il1 = 1.f / lrow[1];
    const size_t orow = (size_t)(b * NQL + q0 + wq + g);
    #pragma unroll
    for (int ni = 0; ni < 8; ni++) {
        const int c = col0 + ni * 8 + 2 * t;
        *(float2*)(O + orow * DIMC + c) =
            make_float2(oacc[ni][0] * il0, oacc[ni][1] * il0);
        *(float2*)(O + (orow + 8) * DIMC + c) =
            make_float2(oacc[ni][2] * il1, oacc[ni][3] * il1);
    }
}

// ============================================================
// Launch
// ============================================================
extern "C" void kernel_launch(void* const* d_in, const int* in_sizes, int n_in,
                              void* d_out, int out_size)
{
    (void)in_sizes; (void)n_in; (void)out_size;
    const float* qf  = (const float*)d_in[0];
    const float* kvf = (const float*)d_in[1];
    const float* rel = (const float*)d_in[2];
    const float* Wq  = (const float*)d_in[3];
    const float* bq  = (const float*)d_in[4];
    const float* Wk  = (const float*)d_in[5];
    const float* bk  = (const float*)d_in[6];
    const float* Wv  = (const float*)d_in[7];
    const float* bv  = (const float*)d_in[8];
    const float* Wo  = (const float*)d_in[9];
    const float* bo  = (const float*)d_in[10];
    float* out = (float*)d_out;

    float *pq, *pk, *pv, *pao;
    cudaGetSymbolAddress((void**)&pq,  g_q);
    cudaGetSymbolAddress((void**)&pk,  g_k);
    cudaGetSymbolAddress((void**)&pv,  g_v);
    cudaGetSymbolAddress((void**)&pao, g_ao);

    const int gemm_smem  = (int)(2 * BM * SAo + 2 * BN * SAo) * 4;        // 73728 B
    const int flash_smem = (int)(128 * SQ + 64 * SQ + 64 * SQ + 128 * SQ + 64) * 4; // 104704 B

    cudaFuncSetAttribute(gemm_nt<false>, cudaFuncAttributeMaxDynamicSharedMemorySize, gemm_smem);
    cudaFuncSetAttribute(gemm_nt<true>,  cudaFuncAttributeMaxDynamicSharedMemorySize, gemm_smem);
    cudaFuncSetAttribute(flash_attn,     cudaFuncAttributeMaxDynamicSharedMemorySize, flash_smem);

    dim3 gg(DIMC / BN, MROWS / BM);   // (8, 32)
    gemm_nt<false><<<gg, 256, gemm_smem>>>(qf,  Wq, bq, nullptr, pq,  MROWS, DIMC, DIMC);
    gemm_nt<true ><<<gg, 256, gemm_smem>>>(kvf, Wk, bk, rel,     pk,  MROWS, DIMC, DIMC);
    gemm_nt<true ><<<gg, 256, gemm_smem>>>(kvf, Wv, bv, rel,     pv,  MROWS, DIMC, DIMC);

    flash_attn<<<dim3(NQL / 128, HEADS, BATCH), 256, flash_smem>>>(pq, pk, pv, rel, pao);

    gemm_nt<false><<<gg, 256, gemm_smem>>>(pao, Wo, bo, nullptr, out, MROWS, DIMC, DIMC);
}

// round 6
// speedup vs baseline: 1.0036x; 1.0036x over previous
#include <cuda_runtime.h>
#include <math.h>
#include <stdint.h>

// ============================================================
// ReliabilityGatedCrossAttention  (B=4, N=1024, DIM=1024, H=16, d=64)
// tf32 mma.sync everywhere; fragment-layout smem (vector LDS, swizzled).
// ============================================================

#define DIMC   1024
#define HEADS  16
#define HDIM   64
#define BATCH  4
#define NQL    1024
#define NKVL   1024
#define MROWS  (BATCH * NQL)   // 4096

// -------- scratch (no allocations allowed) --------
__device__ float g_q [(size_t)MROWS * DIMC];
__device__ float g_k [(size_t)MROWS * DIMC];
__device__ float g_v [(size_t)MROWS * DIMC];
__device__ float g_ao[(size_t)MROWS * DIMC];

// -------- helpers --------
__device__ __forceinline__ float f2tf32(float x) {
    uint32_t u;
    asm("cvt.rna.tf32.f32 %0, %1;" : "=r"(u) : "f"(x));
    return __uint_as_float(u);
}

__device__ __forceinline__ void mma_tf32(float c[4], const uint32_t a[4], const uint32_t b[2]) {
    asm volatile(
        "mma.sync.aligned.m16n8k8.row.col.f32.tf32.tf32.f32 "
        "{%0,%1,%2,%3},{%4,%5,%6,%7},{%8,%9},{%0,%1,%2,%3};\n"
        : "+f"(c[0]), "+f"(c[1]), "+f"(c[2]), "+f"(c[3])
        : "r"(a[0]), "r"(a[1]), "r"(a[2]), "r"(a[3]), "r"(b[0]), "r"(b[1]));
}

// ============================================================
// GEMM-NT:  C[m,n] = (sum_k A[m,k]*W[n,k] + bias[n]) * (GATE ? gate[m] : 1)
// BM=BN=128, BK=32, 256 threads.  Fragment-layout smem:
//   A-frag: Af[mi(8)][ks(4)][lane(32)][4]  -> LDS.128 per (mi,ks)
//   B-frag: Bf[nb(16)][ks(4)][lane(32)][2] -> LDS.64  per (nb,ks)
// lane slot = g*4 + (t ^ swz); A swz=(ks+2*(g>>1))&3, B swz=ks&3.
// ============================================================
#define BM 128
#define BN 128
#define BK 32

template<bool GATE>
__global__ __launch_bounds__(256, 2)
void gemm_nt(const float* __restrict__ A, const float* __restrict__ W,
             const float* __restrict__ bias, const float* __restrict__ gate,
             float* __restrict__ C, int M, int N, int K)
{
    extern __shared__ float sm[];
    // [buf][4096] A-frags, then [buf][4096] B-frags
    float* Af = sm;
    float* Bf = sm + 8192;

    const int tid  = threadIdx.x;
    const int wid  = tid >> 5;
    const int lane = tid & 31;
    const int g    = lane >> 2;
    const int t    = lane & 3;
    const int m0 = blockIdx.y * BM;
    const int n0 = blockIdx.x * BN;
    const int miB = (wid >> 2) * 4;   // warp mi-block base (4 blocks of 16 rows)
    const int nbB = (wid & 3) * 4;    // warp nb-block base (4 blocks of 8 cols)

    const int lr  = tid >> 3;          // 0..31
    const int lc  = (tid & 7) * 4;     // 0..28
    const int ksL = lc >> 3;
    const int hkL = (lc >> 2) & 1;

    float acc[4][4][4];
    #pragma unroll
    for (int i = 0; i < 4; i++)
        #pragma unroll
        for (int j = 0; j < 4; j++)
            #pragma unroll
            for (int c = 0; c < 4; c++) acc[i][j][c] = 0.f;

    const float* Ag = A + (size_t)(m0 + lr) * K + lc;
    const float* Bg = W + (size_t)(n0 + lr) * K + lc;

    float4 ra[4], rb[4];
    #pragma unroll
    for (int i = 0; i < 4; i++) {
        ra[i] = *(const float4*)(Ag + (size_t)(32 * i) * K);
        rb[i] = *(const float4*)(Bg + (size_t)(32 * i) * K);
    }

    // scatter-store one (A,B) tile into frag layout at buffer `buf`
    auto scatter = [&](int buf, const float4* pa, const float4* pb) {
        float* Ad = Af + buf * 4096;
        float* Bd = Bf + buf * 4096;
        #pragma unroll
        for (int i = 0; i < 4; i++) {
            const int row = lr + 32 * i;
            // A element (row, lc+e)
            {
                const int mi = row >> 4, g3 = row & 7, hR = (row >> 3) & 1;
                const int jA = hR + 2 * hkL;
                float* base = Ad + ((mi * 4 + ksL) * 32) * 4 + jA;
                const int sA = (ksL + 2 * (g3 >> 1)) & 3;
                const float v[4] = {pa[i].x, pa[i].y, pa[i].z, pa[i].w};
                #pragma unroll
                for (int e = 0; e < 4; e++)
                    base[(g3 * 4 + (e ^ sA)) * 4] = f2tf32(v[e]);
            }
            // B element (row, lc+e)
            {
                const int nb = row >> 3, g3 = row & 7;
                float* base = Bd + ((nb * 4 + ksL) * 32) * 2 + hkL;
                const int sB = ksL & 3;
                const float v[4] = {pb[i].x, pb[i].y, pb[i].z, pb[i].w};
                #pragma unroll
                for (int e = 0; e < 4; e++)
                    base[(g3 * 4 + (e ^ sB)) * 2] = f2tf32(v[e]);
            }
        }
    };

    scatter(0, ra, rb);

    int buf = 0;
    const int KT = K / BK;
    for (int kt = 0; kt < KT; kt++) {
        __syncthreads();
        const bool more = (kt + 1 < KT);
        if (more) {
            const float* Ag2 = Ag + (kt + 1) * BK;
            const float* Bg2 = Bg + (kt + 1) * BK;
            #pragma unroll
            for (int i = 0; i < 4; i++) {
                ra[i] = *(const float4*)(Ag2 + (size_t)(32 * i) * K);
                rb[i] = *(const float4*)(Bg2 + (size_t)(32 * i) * K);
            }
        }
        const float* Ab = Af + buf * 4096;
        const float* Bb = Bf + buf * 4096;
        #pragma unroll
        for (int ks = 0; ks < 4; ks++) {
            float4 a4[4];
            #pragma unroll
            for (int mi = 0; mi < 4; mi++) {
                const int slot = g * 4 + (t ^ ((ks + 2 * (g >> 1)) & 3));
                a4[mi] = *(const float4*)(Ab + (((miB + mi) * 4 + ks) * 32 + slot) * 4);
            }
            float2 b2[4];
            #pragma unroll
            for (int ni = 0; ni < 4; ni++) {
                const int slot = g * 4 + (t ^ (ks & 3));
                b2[ni] = *(const float2*)(Bb + (((nbB + ni) * 4 + ks) * 32 + slot) * 2);
            }
            #pragma unroll
            for (int mi = 0; mi < 4; mi++) {
                const uint32_t* af = (const uint32_t*)&a4[mi];
                #pragma unroll
                for (int ni = 0; ni < 4; ni++)
                    mma_tf32(acc[mi][ni], af, (const uint32_t*)&b2[ni]);
            }
        }
        if (more) scatter(buf ^ 1, ra, rb);
        buf ^= 1;
    }

    // epilogue
    #pragma unroll
    for (int ni = 0; ni < 4; ni++) {
        const int cc = n0 + (nbB + ni) * 8 + 2 * t;
        const float b0 = bias[cc];
        const float b1 = bias[cc + 1];
        #pragma unroll
        for (int mi = 0; mi < 4; mi++) {
            const int rr = m0 + (miB + mi) * 16 + g;
            float v0 = acc[mi][ni][0] + b0;
            float v1 = acc[mi][ni][1] + b1;
            float v2 = acc[mi][ni][2] + b0;
            float v3 = acc[mi][ni][3] + b1;
            if (GATE) {
                const float g0 = gate[rr];
                const float g1 = gate[rr + 8];
                v0 *= g0; v1 *= g0; v2 *= g1; v3 *= g1;
            }
            *(float2*)(C + (size_t)rr * N + cc)       = make_float2(v0, v1);
            *(float2*)(C + (size_t)(rr + 8) * N + cc) = make_float2(v2, v3);
        }
    }
}

// ============================================================
// Flash attention: 128 threads (4 warps), each warp 32 q-rows.
// Q fragments persistent in registers.  K/V/P in frag-layout smem.
//   Kf/Vf: [nb(8)][ks(8)][lane(32)][2]   slot = (g^(ks>>2))*4 + (t^((nb^ks)&3))
//   Pf (per warp,mi): [ks(8)][lane(32)][4]  slot = g*4 + (t^((g>>1)&3))
// ============================================================
#define KF_OFF   0
#define VF_OFF   4096
#define PF_OFF   8192     // 8192 floats
#define SLR_OFF  16384    // 64 floats
#define QS_OFF   8192     // staging alias (128*68 = 8704 floats, dead after prologue)
#define QS_STR   68
#define FATT_FLOATS 16896

__global__ __launch_bounds__(128, 2)
void flash_attn(const float* __restrict__ Q, const float* __restrict__ Kg,
                const float* __restrict__ V, const float* __restrict__ rel,
                float* __restrict__ O)
{
    extern __shared__ float sm[];
    float* Kf  = sm + KF_OFF;
    float* Vf  = sm + VF_OFF;
    float* Pf  = sm + PF_OFF;
    float* slr = sm + SLR_OFF;
    float* Qs  = sm + QS_OFF;

    const int tid  = threadIdx.x;
    const int wid  = tid >> 5;
    const int lane = tid & 31;
    const int g    = lane >> 2;
    const int t    = lane & 3;
    const int q0   = blockIdx.x * 128;
    const int h    = blockIdx.y;
    const int b    = blockIdx.z;
    const int col0 = h * HDIM;
    const int wq   = wid * 32;

    // ---- stage Q tile (coalesced), extract frags to registers ----
    #pragma unroll
    for (int i = 0; i < 16; i++) {
        const int chunk = tid + 128 * i;
        const int row = chunk >> 4;
        const int c4  = (chunk & 15) * 4;
        float4 v = *(const float4*)(Q + (size_t)(b * NQL + q0 + row) * DIMC + col0 + c4);
        v.x = f2tf32(v.x); v.y = f2tf32(v.y); v.z = f2tf32(v.z); v.w = f2tf32(v.w);
        *(float4*)(Qs + row * QS_STR + c4) = v;
    }
    __syncthreads();

    uint32_t qf[2][8][4];
    #pragma unroll
    for (int mi = 0; mi < 2; mi++)
        #pragma unroll
        for (int ks = 0; ks < 8; ks++) {
            const float* p = Qs + (wq + mi * 16 + g) * QS_STR + ks * 8 + t;
            qf[mi][ks][0] = __float_as_uint(p[0]);
            qf[mi][ks][1] = __float_as_uint(p[8 * QS_STR]);
            qf[mi][ks][2] = __float_as_uint(p[4]);
            qf[mi][ks][3] = __float_as_uint(p[8 * QS_STR + 4]);
        }

    float mrow[2][2], lrow[2][2];
    #pragma unroll
    for (int mi = 0; mi < 2; mi++) { mrow[mi][0] = mrow[mi][1] = -1e30f; lrow[mi][0] = lrow[mi][1] = 0.f; }
    float oacc[2][8][4];
    #pragma unroll
    for (int mi = 0; mi < 2; mi++)
        #pragma unroll
        for (int nb = 0; nb < 8; nb++)
            #pragma unroll
            for (int c = 0; c < 4; c++) oacc[mi][nb][c] = 0.f;

    for (int kt = 0; kt < NKVL / 64; kt++) {
        __syncthreads();   // prev tile consumed; Qs dead after first sync
        // ---- load K,V tile into frag layouts ----
        {
            const int r0 = tid >> 4;          // 0..7
            const int c4 = (tid & 15) * 4;    // 0..60
            const int ksK = c4 >> 3;
            const int hkK = (c4 >> 2) & 1;
            #pragma unroll
            for (int i = 0; i < 8; i++) {
                const int row = r0 + 8 * i;   // 0..63
                const size_t go = (size_t)(b * NKVL + kt * 64 + row) * DIMC + col0 + c4;
                float4 kv4 = *(const float4*)(Kg + go);
                float4 vv4 = *(const float4*)(V  + go);
                const float kv[4] = {f2tf32(kv4.x), f2tf32(kv4.y), f2tf32(kv4.z), f2tf32(kv4.w)};
                const float vv[4] = {f2tf32(vv4.x), f2tf32(vv4.y), f2tf32(vv4.z), f2tf32(vv4.w)};
                // K frag: element (kv=row, d=c4+e)
                {
                    const int nb = row >> 3, g3 = row & 7;
                    const int gs = g3 ^ (ksK >> 2);
                    float* base = Kf + ((nb * 8 + ksK) * 32) * 2 + hkK;
                    #pragma unroll
                    for (int e = 0; e < 4; e++)
                        base[(gs * 4 + (e ^ ((nb ^ ksK) & 3))) * 2] = kv[e];
                }
                // V frag: element (kv=row, d=c4+e): nb=d>>3, g3=d&7, ks=row>>3
                {
                    const int ksV = row >> 3, tV = row & 3, hkV = (row >> 2) & 1;
                    const int nbV = c4 >> 3;            // (c4+e)>>3 constant for e<4
                    const int g3b = c4 & 7;             // g3 = g3b + e
                    #pragma unroll
                    for (int e = 0; e < 4; e++) {
                        const int gs = (g3b + e) ^ (ksV >> 2);
                        Vf[((nbV * 8 + ksV) * 32 + gs * 4 + (tV ^ ((nbV ^ ksV) & 3))) * 2 + hkV] = vv[e];
                    }
                }
            }
            if (tid < 64) {
                const float rv = rel[b * NKVL + kt * 64 + tid];
                slr[tid] = logf(fmaxf(rv, 1e-6f));
            }
        }
        __syncthreads();

        // ---- S = Q K^T : both 16-row halves share each B-frag ----
        float sacc[2][8][4];
        #pragma unroll
        for (int mi = 0; mi < 2; mi++)
            #pragma unroll
            for (int nb = 0; nb < 8; nb++)
                #pragma unroll
                for (int c = 0; c < 4; c++) sacc[mi][nb][c] = 0.f;
        #pragma unroll
        for (int ks = 0; ks < 8; ks++) {
            #pragma unroll
            for (int nb = 0; nb < 8; nb++) {
                const int slot = (g ^ (ks >> 2)) * 4 + (t ^ ((nb ^ ks) & 3));
                float2 bv = *(const float2*)(Kf + ((nb * 8 + ks) * 32 + slot) * 2);
                mma_tf32(sacc[0][nb], qf[0][ks], (const uint32_t*)&bv);
                mma_tf32(sacc[1][nb], qf[1][ks], (const uint32_t*)&bv);
            }
        }

        // ---- softmax per 16-row half; write P in PV A-frag layout ----
        #pragma unroll
        for (int mi = 0; mi < 2; mi++) {
            float mt0 = -1e30f, mt1 = -1e30f;
            #pragma unroll
            for (int nb = 0; nb < 8; nb++) {
                const int c = nb * 8 + 2 * t;
                const float l0 = slr[c], l1 = slr[c + 1];
                sacc[mi][nb][0] = sacc[mi][nb][0] * 0.125f + l0;
                sacc[mi][nb][1] = sacc[mi][nb][1] * 0.125f + l1;
                sacc[mi][nb][2] = sacc[mi][nb][2] * 0.125f + l0;
                sacc[mi][nb][3] = sacc[mi][nb][3] * 0.125f + l1;
                mt0 = fmaxf(mt0, fmaxf(sacc[mi][nb][0], sacc[mi][nb][1]));
                mt1 = fmaxf(mt1, fmaxf(sacc[mi][nb][2], sacc[mi][nb][3]));
            }
            mt0 = fmaxf(mt0, __shfl_xor_sync(0xffffffffu, mt0, 1));
            mt0 = fmaxf(mt0, __shfl_xor_sync(0xffffffffu, mt0, 2));
            mt1 = fmaxf(mt1, __shfl_xor_sync(0xffffffffu, mt1, 1));
            mt1 = fmaxf(mt1, __shfl_xor_sync(0xffffffffu, mt1, 2));
            const float mn0 = fmaxf(mrow[mi][0], mt0);
            const float mn1 = fmaxf(mrow[mi][1], mt1);

            const int t2 = (2 * t) & 3;
            const int hk = t >> 1;
            const int sg = (g >> 1) & 3;
            float* pw = Pf + ((wid * 2 + mi) * 8) * 128;
            float rs0 = 0.f, rs1 = 0.f;
            #pragma unroll
            for (int nb = 0; nb < 8; nb++) {
                const float p0 = __expf(sacc[mi][nb][0] - mn0);
                const float p1 = __expf(sacc[mi][nb][1] - mn0);
                const float p2 = __expf(sacc[mi][nb][2] - mn1);
                const float p3 = __expf(sacc[mi][nb][3] - mn1);
                rs0 += p0 + p1;
                rs1 += p2 + p3;
                float* base = pw + nb * 128;
                const int l0s = g * 4 + (t2 ^ sg);
                const int l1s = g * 4 + ((t2 + 1) ^ sg);
                *(float2*)(base + l0s * 4 + 2 * hk) = make_float2(f2tf32(p0), f2tf32(p2));
                *(float2*)(base + l1s * 4 + 2 * hk) = make_float2(f2tf32(p1), f2tf32(p3));
            }
            rs0 += __shfl_xor_sync(0xffffffffu, rs0, 1);
            rs0 += __shfl_xor_sync(0xffffffffu, rs0, 2);
            rs1 += __shfl_xor_sync(0xffffffffu, rs1, 1);
            rs1 += __shfl_xor_sync(0xffffffffu, rs1, 2);

            const float al0 = __expf(mrow[mi][0] - mn0);
            const float al1 = __expf(mrow[mi][1] - mn1);
            lrow[mi][0] = lrow[mi][0] * al0 + rs0;
            lrow[mi][1] = lrow[mi][1] * al1 + rs1;
            mrow[mi][0] = mn0; mrow[mi][1] = mn1;
            #pragma unroll
            for (int nb = 0; nb < 8; nb++) {
                oacc[mi][nb][0] *= al0; oacc[mi][nb][1] *= al0;
                oacc[mi][nb][2] *= al1; oacc[mi][nb][3] *= al1;
            }
        }
        __syncwarp();   // Pf is per-warp private

        // ---- O += P V ----
        #pragma unroll
        for (int ks = 0; ks < 8; ks++) {
            const int pslot = g * 4 + (t ^ ((g >> 1) & 3));
            float4 a0 = *(const float4*)(Pf + ((wid * 2 + 0) * 8 + ks) * 128 + pslot * 4);
            float4 a1 = *(const float4*)(Pf + ((wid * 2 + 1) * 8 + ks) * 128 + pslot * 4);
            #pragma unroll
            for (int nb = 0; nb < 8; nb++) {
                const int slot = (g ^ (ks >> 2)) * 4 + (t ^ ((nb ^ ks) & 3));
                float2 bv = *(const float2*)(Vf + ((nb * 8 + ks) * 32 + slot) * 2);
                mma_tf32(oacc[0][nb], (const uint32_t*)&a0, (const uint32_t*)&bv);
                mma_tf32(oacc[1][nb], (const uint32_t*)&a1, (const uint32_t*)&bv);
            }
        }
    }

    // ---- epilogue ----
    #pragma unroll
    for (int mi = 0; mi < 2; mi++) {
        const float il0 = 1.f / lrow[mi][0];
        const float il1 = 1.f / lrow[mi][1];
        const size_t orow = (size_t)(b * NQL + q0 + wq + mi * 16 + g);
        #pragma unroll
        for (int nb = 0; nb < 8; nb++) {
            const int c = col0 + nb * 8 + 2 * t;
            *(float2*)(O + orow * DIMC + c) =
                make_float2(oacc[mi][nb][0] * il0, oacc[mi][nb][1] * il0);
            *(float2*)(O + (orow + 8) * DIMC + c) =
                make_float2(oacc[mi][nb][2] * il1, oacc[mi][nb][3] * il1);
        }
    }
}

// ============================================================
// Launch
// ============================================================
extern "C" void kernel_launch(void* const* d_in, const int* in_sizes, int n_in,
                              void* d_out, int out_size)
{
    (void)in_sizes; (void)n_in; (void)out_size;
    const float* qf  = (const float*)d_in[0];
    const float* kvf = (const float*)d_in[1];
    const float* rel = (const float*)d_in[2];
    const float* Wq  = (const float*)d_in[3];
    const float* bq  = (const float*)d_in[4];
    const float* Wk  = (const float*)d_in[5];
    const float* bk  = (const float*)d_in[6];
    const float* Wv  = (const float*)d_in[7];
    const float* bv  = (const float*)d_in[8];
    const float* Wo  = (const float*)d_in[9];
    const float* bo  = (const float*)d_in[10];
    float* out = (float*)d_out;

    float *pq, *pk, *pv, *pao;
    cudaGetSymbolAddress((void**)&pq,  g_q);
    cudaGetSymbolAddress((void**)&pk,  g_k);
    cudaGetSymbolAddress((void**)&pv,  g_v);
    cudaGetSymbolAddress((void**)&pao, g_ao);

    const int gemm_smem  = 16384 * 4;         // 64 KB
    const int flash_smem = FATT_FLOATS * 4;   // ~66 KB

    cudaFuncSetAttribute(gemm_nt<false>, cudaFuncAttributeMaxDynamicSharedMemorySize, gemm_smem);
    cudaFuncSetAttribute(gemm_nt<true>,  cudaFuncAttributeMaxDynamicSharedMemorySize, gemm_smem);
    cudaFuncSetAttribute(flash_attn,     cudaFuncAttributeMaxDynamicSharedMemorySize, flash_smem);

    dim3 gg(DIMC / BN, MROWS / BM);   // (8, 32)
    gemm_nt<false><<<gg, 256, gemm_smem>>>(qf,  Wq, bq, nullptr, pq,  MROWS, DIMC, DIMC);
    gemm_nt<true ><<<gg, 256, gemm_smem>>>(kvf, Wk, bk, rel,     pk,  MROWS, DIMC, DIMC);
    gemm_nt<true ><<<gg, 256, gemm_smem>>>(kvf, Wv, bv, rel,     pv,  MROWS, DIMC, DIMC);

    flash_attn<<<dim3(NQL / 128, HEADS, BATCH), 128, flash_smem>>>(pq, pk, pv, rel, pao);

    gemm_nt<false><<<gg, 256, gemm_smem>>>(pao, Wo, bo, nullptr, out, MROWS, DIMC, DIMC);
}

// round 8
// speedup vs baseline: 1.0642x; 1.0603x over previous
#include <cuda_runtime.h>
#include <math.h>
#include <stdint.h>

// ============================================================
// ReliabilityGatedCrossAttention  (B=4, N=1024, DIM=1024, H=16, d=64)
// All matmuls via mma.sync m16n8k8 tf32 (plain sm_103 target: no tcgen05).
// GEMM: R3 proven design. Flash: double-buffered K/V, 1 sync/tile.
// ============================================================

#define DIMC   1024
#define HEADS  16
#define HDIM   64
#define BATCH  4
#define NQL    1024
#define NKVL   1024
#define MROWS  (BATCH * NQL)   // 4096

// -------- scratch (no allocations allowed) --------
__device__ float g_q  [(size_t)MROWS * DIMC];
__device__ float g_k  [(size_t)MROWS * DIMC];
__device__ float g_v  [(size_t)MROWS * DIMC];
__device__ float g_ao [(size_t)MROWS * DIMC];
__device__ float g_slr[(size_t)BATCH * NKVL];

// -------- helpers --------
__device__ __forceinline__ float f2tf32(float x) {
    uint32_t u;
    asm("cvt.rna.tf32.f32 %0, %1;" : "=r"(u) : "f"(x));
    return __uint_as_float(u);
}

__device__ __forceinline__ void mma_tf32(float c[4], const uint32_t a[4], const uint32_t b[2]) {
    asm volatile(
        "mma.sync.aligned.m16n8k8.row.col.f32.tf32.tf32.f32 "
        "{%0,%1,%2,%3},{%4,%5,%6,%7},{%8,%9},{%0,%1,%2,%3};\n"
        : "+f"(c[0]), "+f"(c[1]), "+f"(c[2]), "+f"(c[3])
        : "r"(a[0]), "r"(a[1]), "r"(a[2]), "r"(a[3]), "r"(b[0]), "r"(b[1]));
}

// ============================================================
// prep: slr[i] = log(max(rel[i], 1e-6))
// ============================================================
__global__ void prep_slr(const float* __restrict__ rel, float* __restrict__ slr)
{
    const int i = blockIdx.x * 256 + threadIdx.x;
    slr[i] = logf(fmaxf(rel[i], 1e-6f));
}

// ============================================================
// GEMM-NT (R3 proven):  C[m,n] = (sum_k A[m,k]*W[n,k] + bias[n]) * (GATE?gate[m]:1)
// A: MxK row-major, W: NxK row-major.  BM=BN=128, BK=32, 256 threads.
// smem stride 36 (== 4 mod 32) -> conflict-free fragment LDS.
// ============================================================
#define BM 128
#define BN 128
#define BK 32
#define SAo 36   // padded smem row stride (floats)

template<bool GATE>
__global__ __launch_bounds__(256)
void gemm_nt(const float* __restrict__ A, const float* __restrict__ W,
             const float* __restrict__ bias, const float* __restrict__ gate,
             float* __restrict__ C, int M, int N, int K)
{
    extern __shared__ float sm[];
    float* As = sm;                       // [2][BM][SAo]
    float* Bs = sm + 2 * BM * SAo;        // [2][BN][SAo]

    const int tid  = threadIdx.x;
    const int wid  = tid >> 5;
    const int lane = tid & 31;
    const int g    = lane >> 2;           // group id (row within frag)
    const int t    = lane & 3;            // thread-in-group
    const int m0 = blockIdx.y * BM;
    const int n0 = blockIdx.x * BN;
    const int wm = (wid >> 2) * 64;       // warp m-offset (2 warps in M)
    const int wn = (wid & 3) * 32;        // warp n-offset (4 warps in N)

    const int lr = tid >> 3;              // 0..31 (tile row)
    const int lc = (tid & 7) * 4;         // 0..28 (tile col, float4)

    float acc[4][4][4];
    #pragma unroll
    for (int i = 0; i < 4; i++)
        #pragma unroll
        for (int j = 0; j < 4; j++)
            #pragma unroll
            for (int c = 0; c < 4; c++) acc[i][j][c] = 0.f;

    const float* Ag = A + (size_t)(m0 + lr) * K + lc;
    const float* Bg = W + (size_t)(n0 + lr) * K + lc;

    float4 ra[4], rb[4];
    #pragma unroll
    for (int i = 0; i < 4; i++) {
        ra[i] = *(const float4*)(Ag + (size_t)(32 * i) * K);
        rb[i] = *(const float4*)(Bg + (size_t)(32 * i) * K);
    }
    #pragma unroll
    for (int i = 0; i < 4; i++) {
        float4 a = ra[i];
        a.x = f2tf32(a.x); a.y = f2tf32(a.y); a.z = f2tf32(a.z); a.w = f2tf32(a.w);
        *(float4*)(As + (lr + 32 * i) * SAo + lc) = a;
        float4 bt = rb[i];
        bt.x = f2tf32(bt.x); bt.y = f2tf32(bt.y); bt.z = f2tf32(bt.z); bt.w = f2tf32(bt.w);
        *(float4*)(Bs + (lr + 32 * i) * SAo + lc) = bt;
    }

    int buf = 0;
    const int KT = K / BK;
    for (int kt = 0; kt < KT; kt++) {
        __syncthreads();
        const bool more = (kt + 1 < KT);
        if (more) {
            const float* Ag2 = Ag + (kt + 1) * BK;
            const float* Bg2 = Bg + (kt + 1) * BK;
            #pragma unroll
            for (int i = 0; i < 4; i++) {
                ra[i] = *(const float4*)(Ag2 + (size_t)(32 * i) * K);
                rb[i] = *(const float4*)(Bg2 + (size_t)(32 * i) * K);
            }
        }
        const float* Ab = As + buf * BM * SAo + wm * SAo;
        const float* Bb = Bs + buf * BN * SAo + wn * SAo;
        #pragma unroll
        for (int ks = 0; ks < 4; ks++) {
            const int kk = ks * 8;
            uint32_t af[4][4];
            #pragma unroll
            for (int mi = 0; mi < 4; mi++) {
                const float* p = Ab + (mi * 16 + g) * SAo + kk + t;
                af[mi][0] = __float_as_uint(p[0]);
                af[mi][1] = __float_as_uint(p[8 * SAo]);
                af[mi][2] = __float_as_uint(p[4]);
                af[mi][3] = __float_as_uint(p[8 * SAo + 4]);
            }
            uint32_t bf[4][2];
            #pragma unroll
            for (int ni = 0; ni < 4; ni++) {
                const float* p = Bb + (ni * 8 + g) * SAo + kk + t;
                bf[ni][0] = __float_as_uint(p[0]);
                bf[ni][1] = __float_as_uint(p[4]);
            }
            #pragma unroll
            for (int mi = 0; mi < 4; mi++)
                #pragma unroll
                for (int ni = 0; ni < 4; ni++)
                    mma_tf32(acc[mi][ni], af[mi], bf[ni]);
        }
        if (more) {
            float* Ad = As + (buf ^ 1) * BM * SAo;
            float* Bd = Bs + (buf ^ 1) * BN * SAo;
            #pragma unroll
            for (int i = 0; i < 4; i++) {
                float4 a = ra[i];
                a.x = f2tf32(a.x); a.y = f2tf32(a.y); a.z = f2tf32(a.z); a.w = f2tf32(a.w);
                *(float4*)(Ad + (lr + 32 * i) * SAo + lc) = a;
                float4 bt = rb[i];
                bt.x = f2tf32(bt.x); bt.y = f2tf32(bt.y); bt.z = f2tf32(bt.z); bt.w = f2tf32(bt.w);
                *(float4*)(Bd + (lr + 32 * i) * SAo + lc) = bt;
            }
        }
        buf ^= 1;
    }

    // epilogue
    #pragma unroll
    for (int ni = 0; ni < 4; ni++) {
        const int cc = n0 + wn + ni * 8 + 2 * t;
        const float b0 = bias[cc];
        const float b1 = bias[cc + 1];
        #pragma unroll
        for (int mi = 0; mi < 4; mi++) {
            const int rr = m0 + wm + mi * 16 + g;
            float v0 = acc[mi][ni][0] + b0;
            float v1 = acc[mi][ni][1] + b1;
            float v2 = acc[mi][ni][2] + b0;
            float v3 = acc[mi][ni][3] + b1;
            if (GATE) {
                const float g0 = gate[rr];
                const float g1 = gate[rr + 8];
                v0 *= g0; v1 *= g0; v2 *= g1; v3 *= g1;
            }
            *(float2*)(C + (size_t)rr * N + cc)       = make_float2(v0, v1);
            *(float2*)(C + (size_t)(rr + 8) * N + cc) = make_float2(v2, v3);
        }
    }
}

// ============================================================
// Flash attention: 128 threads (4 warps), each warp 32 q-rows.
// Q frags persistent in registers.  K/V double-buffered frag-layout smem;
// ONE __syncthreads per KV tile; prefetch LDGs overlap MMA.
//   Kf/Vf: [nb(8)][ks(8)][lane(32)][2]  slot = (g^(ks>>2))*4 + (t^((nb^ks)&3))
//   Pf (per warp,mi): [ks(8)][lane(32)][4]  slot = g*4 + (t^((g>>1)&3))
// ============================================================
#define KF0_OFF   0
#define KF1_OFF   4096
#define VF0_OFF   8192
#define VF1_OFF   12288
#define PF_OFF    16384   // 8192 floats -> 24576
#define SLR_OFF   24576   // [2][64]
#define QS_OFF    8192    // staging alias over VF/PF head (dead after prologue)
#define QS_STR    68
#define FATT_FLOATS 24704

__global__ __launch_bounds__(128, 2)
void flash_attn(const float* __restrict__ Q, const float* __restrict__ Kg,
                const float* __restrict__ V, const float* __restrict__ slrg,
                float* __restrict__ O)
{
    extern __shared__ float sm[];
    float* Pf  = sm + PF_OFF;
    float* Qs  = sm + QS_OFF;

    const int tid  = threadIdx.x;
    const int wid  = tid >> 5;
    const int lane = tid & 31;
    const int g    = lane >> 2;
    const int t    = lane & 3;
    const int q0   = blockIdx.x * 128;
    const int h    = blockIdx.y;
    const int b    = blockIdx.z;
    const int col0 = h * HDIM;
    const int wq   = wid * 32;

    // ---- stage Q tile (coalesced), extract frags to registers ----
    #pragma unroll
    for (int i = 0; i < 16; i++) {
        const int chunk = tid + 128 * i;
        const int row = chunk >> 4;
        const int c4  = (chunk & 15) * 4;
        float4 v = *(const float4*)(Q + (size_t)(b * NQL + q0 + row) * DIMC + col0 + c4);
        v.x = f2tf32(v.x); v.y = f2tf32(v.y); v.z = f2tf32(v.z); v.w = f2tf32(v.w);
        *(float4*)(Qs + row * QS_STR + c4) = v;
    }
    __syncthreads();

    uint32_t qf[2][8][4];
    #pragma unroll
    for (int mi = 0; mi < 2; mi++)
        #pragma unroll
        for (int ks = 0; ks < 8; ks++) {
            const float* p = Qs + (wq + mi * 16 + g) * QS_STR + ks * 8 + t;
            qf[mi][ks][0] = __float_as_uint(p[0]);
            qf[mi][ks][1] = __float_as_uint(p[8 * QS_STR]);
            qf[mi][ks][2] = __float_as_uint(p[4]);
            qf[mi][ks][3] = __float_as_uint(p[8 * QS_STR + 4]);
        }
    __syncthreads();   // Qs dead; smem free for KV buffers

    // loader geometry
    const int r0  = tid >> 4;          // 0..7
    const int c4  = (tid & 15) * 4;    // 0..60
    const int ksK = c4 >> 3;
    const int hkK = (c4 >> 2) & 1;
    const int nbV = c4 >> 3;
    const int g3b = c4 & 7;

    // prefetch tile 0
    float4 rk[8], rv[8];
    #pragma unroll
    for (int i = 0; i < 8; i++) {
        const int row = r0 + 8 * i;
        const size_t go = (size_t)(b * NKVL + row) * DIMC + col0 + c4;
        rk[i] = *(const float4*)(Kg + go);
        rv[i] = *(const float4*)(V  + go);
    }
    float slr_pre = (tid < 64) ? slrg[b * NKVL + tid] : 0.f;

    float mrow[2][2], lrow[2][2];
    #pragma unroll
    for (int mi = 0; mi < 2; mi++) { mrow[mi][0] = mrow[mi][1] = -1e30f; lrow[mi][0] = lrow[mi][1] = 0.f; }
    float oacc[2][8][4];
    #pragma unroll
    for (int mi = 0; mi < 2; mi++)
        #pragma unroll
        for (int nb = 0; nb < 8; nb++)
            #pragma unroll
            for (int c = 0; c < 4; c++) oacc[mi][nb][c] = 0.f;

    int buf = 0;
    for (int kt = 0; kt < NKVL / 64; kt++) {
        float* Kf = sm + (buf ? KF1_OFF : KF0_OFF);
        float* Vf = sm + (buf ? VF1_OFF : VF0_OFF);
        float* sl = sm + SLR_OFF + buf * 64;

        // ---- scatter prefetched tile into frag layouts ----
        #pragma unroll
        for (int i = 0; i < 8; i++) {
            const int row = r0 + 8 * i;
            const float kv[4] = {f2tf32(rk[i].x), f2tf32(rk[i].y), f2tf32(rk[i].z), f2tf32(rk[i].w)};
            const float vv[4] = {f2tf32(rv[i].x), f2tf32(rv[i].y), f2tf32(rv[i].z), f2tf32(rv[i].w)};
            {
                const int nb = row >> 3, g3 = row & 7;
                const int gs = g3 ^ (ksK >> 2);
                float* base = Kf + ((nb * 8 + ksK) * 32) * 2 + hkK;
                #pragma unroll
                for (int e = 0; e < 4; e++)
                    base[(gs * 4 + (e ^ ((nb ^ ksK) & 3))) * 2] = kv[e];
            }
            {
                const int ksV = row >> 3, tV = row & 3, hkV = (row >> 2) & 1;
                #pragma unroll
                for (int e = 0; e < 4; e++) {
                    const int gs = (g3b + e) ^ (ksV >> 2);
                    Vf[((nbV * 8 + ksV) * 32 + gs * 4 + (tV ^ ((nbV ^ ksV) & 3))) * 2 + hkV] = vv[e];
                }
            }
        }
        if (tid < 64) sl[tid] = slr_pre;
        __syncthreads();

        // ---- prefetch next tile K (hidden under QK) ----
        const int ktn = (kt + 1 < NKVL / 64) ? kt + 1 : kt;
        #pragma unroll
        for (int i = 0; i < 8; i++) {
            const int row = r0 + 8 * i;
            rk[i] = *(const float4*)(Kg + (size_t)(b * NKVL + ktn * 64 + row) * DIMC + col0 + c4);
        }
        if (tid < 64) slr_pre = slrg[b * NKVL + ktn * 64 + tid];

        // ---- per 16-row half: S = Q K^T, softmax, write P ----
        #pragma unroll
        for (int mi = 0; mi < 2; mi++) {
            float sacc[8][4];
            #pragma unroll
            for (int nb = 0; nb < 8; nb++)
                #pragma unroll
                for (int c = 0; c < 4; c++) sacc[nb][c] = 0.f;
            #pragma unroll
            for (int ks = 0; ks < 8; ks++) {
                #pragma unroll
                for (int nb = 0; nb < 8; nb++) {
                    const int slot = (g ^ (ks >> 2)) * 4 + (t ^ ((nb ^ ks) & 3));
                    float2 bv = *(const float2*)(Kf + ((nb * 8 + ks) * 32 + slot) * 2);
                    mma_tf32(sacc[nb], qf[mi][ks], (const uint32_t*)&bv);
                }
            }
            float mt0 = -1e30f, mt1 = -1e30f;
            #pragma unroll
            for (int nb = 0; nb < 8; nb++) {
                const int c = nb * 8 + 2 * t;
                const float l0 = sl[c], l1 = sl[c + 1];
                sacc[nb][0] = sacc[nb][0] * 0.125f + l0;
                sacc[nb][1] = sacc[nb][1] * 0.125f + l1;
                sacc[nb][2] = sacc[nb][2] * 0.125f + l0;
                sacc[nb][3] = sacc[nb][3] * 0.125f + l1;
                mt0 = fmaxf(mt0, fmaxf(sacc[nb][0], sacc[nb][1]));
                mt1 = fmaxf(mt1, fmaxf(sacc[nb][2], sacc[nb][3]));
            }
            mt0 = fmaxf(mt0, __shfl_xor_sync(0xffffffffu, mt0, 1));
            mt0 = fmaxf(mt0, __shfl_xor_sync(0xffffffffu, mt0, 2));
            mt1 = fmaxf(mt1, __shfl_xor_sync(0xffffffffu, mt1, 1));
            mt1 = fmaxf(mt1, __shfl_xor_sync(0xffffffffu, mt1, 2));
            const float mn0 = fmaxf(mrow[mi][0], mt0);
            const float mn1 = fmaxf(mrow[mi][1], mt1);

            const int t2 = (2 * t) & 3;
            const int hk = t >> 1;
            const int sg = (g >> 1) & 3;
            float* pw = Pf + ((wid * 2 + mi) * 8) * 128;
            float rs0 = 0.f, rs1 = 0.f;
            #pragma unroll
            for (int nb = 0; nb < 8; nb++) {
                const float p0 = __expf(sacc[nb][0] - mn0);
                const float p1 = __expf(sacc[nb][1] - mn0);
                const float p2 = __expf(sacc[nb][2] - mn1);
                const float p3 = __expf(sacc[nb][3] - mn1);
                rs0 += p0 + p1;
                rs1 += p2 + p3;
                float* base = pw + nb * 128;
                const int l0s = g * 4 + (t2 ^ sg);
                const int l1s = g * 4 + ((t2 + 1) ^ sg);
                *(float2*)(base + l0s * 4 + 2 * hk) = make_float2(f2tf32(p0), f2tf32(p2));
                *(float2*)(base + l1s * 4 + 2 * hk) = make_float2(f2tf32(p1), f2tf32(p3));
            }
            rs0 += __shfl_xor_sync(0xffffffffu, rs0, 1);
            rs0 += __shfl_xor_sync(0xffffffffu, rs0, 2);
            rs1 += __shfl_xor_sync(0xffffffffu, rs1, 1);
            rs1 += __shfl_xor_sync(0xffffffffu, rs1, 2);

            const float al0 = __expf(mrow[mi][0] - mn0);
            const float al1 = __expf(mrow[mi][1] - mn1);
            lrow[mi][0] = lrow[mi][0] * al0 + rs0;
            lrow[mi][1] = lrow[mi][1] * al1 + rs1;
            mrow[mi][0] = mn0; mrow[mi][1] = mn1;
            #pragma unroll
            for (int nb = 0; nb < 8; nb++) {
                oacc[mi][nb][0] *= al0; oacc[mi][nb][1] *= al0;
                oacc[mi][nb][2] *= al1; oacc[mi][nb][3] *= al1;
            }
        }
        __syncwarp();   // Pf is per-warp private

        // ---- prefetch next tile V (hidden under PV) ----
        #pragma unroll
        for (int i = 0; i < 8; i++) {
            const int row = r0 + 8 * i;
            rv[i] = *(const float4*)(V + (size_t)(b * NKVL + ktn * 64 + row) * DIMC + col0 + c4);
        }

        // ---- O += P V ----
        #pragma unroll
        for (int ks = 0; ks < 8; ks++) {
            const int pslot = g * 4 + (t ^ ((g >> 1) & 3));
            float4 a0 = *(const float4*)(Pf + ((wid * 2 + 0) * 8 + ks) * 128 + pslot * 4);
            float4 a1 = *(const float4*)(Pf + ((wid * 2 + 1) * 8 + ks) * 128 + pslot * 4);
            #pragma unroll
            for (int nb = 0; nb < 8; nb++) {
                const int slot = (g ^ (ks >> 2)) * 4 + (t ^ ((nb ^ ks) & 3));
                float2 bv = *(const float2*)(Vf + ((nb * 8 + ks) * 32 + slot) * 2);
                mma_tf32(oacc[0][nb], (const uint32_t*)&a0, (const uint32_t*)&bv);
                mma_tf32(oacc[1][nb], (const uint32_t*)&a1, (const uint32_t*)&bv);
            }
        }
        buf ^= 1;
    }

    // ---- epilogue ----
    #pragma unroll
    for (int mi = 0; mi < 2; mi++) {
        const float il0 = 1.f / lrow[mi][0];
        const float il1 = 1.f / lrow[mi][1];
        const size_t orow = (size_t)(b * NQL + q0 + wq + mi * 16 + g);
        #pragma unroll
        for (int nb = 0; nb < 8; nb++) {
            const int c = col0 + nb * 8 + 2 * t;
            *(float2*)(O + orow * DIMC + c) =
                make_float2(oacc[mi][nb][0] * il0, oacc[mi][nb][1] * il0);
            *(float2*)(O + (orow + 8) * DIMC + c) =
                make_float2(oacc[mi][nb][2] * il1, oacc[mi][nb][3] * il1);
        }
    }
}

// ============================================================
// Launch
// ============================================================
extern "C" void kernel_launch(void* const* d_in, const int* in_sizes, int n_in,
                              void* d_out, int out_size)
{
    (void)in_sizes; (void)n_in; (void)out_size;
    const float* qf  = (const float*)d_in[0];
    const float* kvf = (const float*)d_in[1];
    const float* rel = (const float*)d_in[2];
    const float* Wq  = (const float*)d_in[3];
    const float* bq  = (const float*)d_in[4];
    const float* Wk  = (const float*)d_in[5];
    const float* bk  = (const float*)d_in[6];
    const float* Wv  = (const float*)d_in[7];
    const float* bv  = (const float*)d_in[8];
    const float* Wo  = (const float*)d_in[9];
    const float* bo  = (const float*)d_in[10];
    float* out = (float*)d_out;

    float *pq, *pk, *pv, *pao, *pslr;
    cudaGetSymbolAddress((void**)&pq,   g_q);
    cudaGetSymbolAddress((void**)&pk,   g_k);
    cudaGetSymbolAddress((void**)&pv,   g_v);
    cudaGetSymbolAddress((void**)&pao,  g_ao);
    cudaGetSymbolAddress((void**)&pslr, g_slr);

    const int gemm_smem  = (int)(2 * BM * SAo + 2 * BN * SAo) * 4;   // 73728 B
    const int flash_smem = FATT_FLOATS * 4;                          // 98816 B

    cudaFuncSetAttribute(gemm_nt<false>, cudaFuncAttributeMaxDynamicSharedMemorySize, gemm_smem);
    cudaFuncSetAttribute(gemm_nt<true>,  cudaFuncAttributeMaxDynamicSharedMemorySize, gemm_smem);
    cudaFuncSetAttribute(flash_attn,     cudaFuncAttributeMaxDynamicSharedMemorySize, flash_smem);

    prep_slr<<<BATCH * NKVL / 256, 256>>>(rel, pslr);

    dim3 gg(DIMC / BN, MROWS / BM);   // (8, 32)
    gemm_nt<false><<<gg, 256, gemm_smem>>>(qf,  Wq, bq, nullptr, pq,  MROWS, DIMC, DIMC);
    gemm_nt<true ><<<gg, 256, gemm_smem>>>(kvf, Wk, bk, rel,     pk,  MROWS, DIMC, DIMC);
    gemm_nt<true ><<<gg, 256, gemm_smem>>>(kvf, Wv, bv, rel,     pv,  MROWS, DIMC, DIMC);

    flash_attn<<<dim3(NQL / 128, HEADS, BATCH), 128, flash_smem>>>(pq, pk, pv, pslr, pao);

    gemm_nt<false><<<gg, 256, gemm_smem>>>(pao, Wo, bo, nullptr, out, MROWS, DIMC, DIMC);
}

// round 9
// speedup vs baseline: 1.1655x; 1.0952x over previous
#include <cuda_runtime.h>
#include <math.h>
#include <stdint.h>

// ============================================================
// ReliabilityGatedCrossAttention  (B=4, N=1024, DIM=1024, H=16, d=64)
// All matmuls: mma.sync m16n8k8 tf32.  All tf32 rounding moved to
// producers (prep kernels / epilogues) so GEMM hot loops use cp.async
// with no cvt and no prefetch registers -> 2 CTAs/SM.
// ============================================================

#define DIMC   1024
#define HEADS  16
#define HDIM   64
#define BATCH  4
#define NQL    1024
#define NKVL   1024
#define MROWS  (BATCH * NQL)   // 4096

// -------- scratch (no allocations allowed) --------
__device__ float g_q  [(size_t)MROWS * DIMC];
__device__ float g_k  [(size_t)MROWS * DIMC];
__device__ float g_v  [(size_t)MROWS * DIMC];
__device__ float g_ao [(size_t)MROWS * DIMC];
__device__ float g_xq [(size_t)MROWS * DIMC];   // tf32-rounded query_feat
__device__ float g_xkv[(size_t)MROWS * DIMC];   // tf32-rounded key_value_feat
__device__ float g_wq [(size_t)DIMC * DIMC];
__device__ float g_wk [(size_t)DIMC * DIMC];
__device__ float g_wv [(size_t)DIMC * DIMC];
__device__ float g_wo [(size_t)DIMC * DIMC];
__device__ float g_slr[(size_t)BATCH * NKVL];

// -------- helpers --------
__device__ __forceinline__ float f2tf32(float x) {
    uint32_t u;
    asm("cvt.rna.tf32.f32 %0, %1;" : "=r"(u) : "f"(x));
    return __uint_as_float(u);
}

__device__ __forceinline__ void mma_tf32(float c[4], const uint32_t a[4], const uint32_t b[2]) {
    asm volatile(
        "mma.sync.aligned.m16n8k8.row.col.f32.tf32.tf32.f32 "
        "{%0,%1,%2,%3},{%4,%5,%6,%7},{%8,%9},{%0,%1,%2,%3};\n"
        : "+f"(c[0]), "+f"(c[1]), "+f"(c[2]), "+f"(c[3])
        : "r"(a[0]), "r"(a[1]), "r"(a[2]), "r"(a[3]), "r"(b[0]), "r"(b[1]));
}

__device__ __forceinline__ uint32_t smem_u32(const void* p) {
    uint32_t a;
    asm("{ .reg .u64 t; cvta.to.shared.u64 t, %1; cvt.u32.u64 %0, t; }" : "=r"(a) : "l"(p));
    return a;
}

__device__ __forceinline__ void cp_a16(uint32_t dst, const float* src) {
    asm volatile("cp.async.cg.shared.global [%0], [%1], 16;" :: "r"(dst), "l"(src));
}

// ============================================================
// prep kernels
// ============================================================
__global__ void prep_slr(const float* __restrict__ rel, float* __restrict__ slr)
{
    const int i = blockIdx.x * 256 + threadIdx.x;
    slr[i] = logf(fmaxf(rel[i], 1e-6f));
}

__global__ void conv_tf32(const float* __restrict__ in, float* __restrict__ out)
{
    const int i = blockIdx.x * 256 + threadIdx.x;
    float4 v = ((const float4*)in)[i];
    v.x = f2tf32(v.x); v.y = f2tf32(v.y); v.z = f2tf32(v.z); v.w = f2tf32(v.w);
    ((float4*)out)[i] = v;
}

// ============================================================
// GEMM-NT:  C[m,n] = (sum_k A[m,k]*W[n,k] + bias[n]) * (GATE ? gate[m] : 1)
// Inputs A,W pre-rounded to tf32.  BM=BN=128, BK=32, 256 threads,
// cp.async double-buffered, 2 CTAs/SM.  ROUND: round output to tf32.
// ============================================================
#define BM 128
#define BN 128
#define BK 32
#define SAo 36   // padded smem row stride (floats); frag LDS conflict-free

template<bool GATE, bool ROUND>
__global__ __launch_bounds__(256, 2)
void gemm_nt(const float* __restrict__ A, const float* __restrict__ W,
             const float* __restrict__ bias, const float* __restrict__ gate,
             float* __restrict__ C, int M, int N, int K)
{
    extern __shared__ float sm[];
    const uint32_t sbase = smem_u32(sm);

    const int tid  = threadIdx.x;
    const int wid  = tid >> 5;
    const int lane = tid & 31;
    const int g    = lane >> 2;
    const int t    = lane & 3;
    const int m0 = blockIdx.y * BM;
    const int n0 = blockIdx.x * BN;
    const int wm = (wid >> 2) * 64;
    const int wn = (wid & 3) * 32;

    const int lr = tid >> 3;              // 0..31
    const int lc = (tid & 7) * 4;         // 0..28

    float acc[4][4][4];
    #pragma unroll
    for (int i = 0; i < 4; i++)
        #pragma unroll
        for (int j = 0; j < 4; j++)
            #pragma unroll
            for (int c = 0; c < 4; c++) acc[i][j][c] = 0.f;

    const float* Ag = A + (size_t)(m0 + lr) * K + lc;
    const float* Bg = W + (size_t)(n0 + lr) * K + lc;

    // issue one (A,B) k-tile into stage s
    auto issue_tile = [&](int kt, int s) {
        const int kc = kt * BK;
        #pragma unroll
        for (int i = 0; i < 4; i++) {
            const uint32_t da = sbase +
                (uint32_t)((s * BM * SAo + (lr + 32 * i) * SAo + lc) * 4);
            cp_a16(da, Ag + (size_t)(32 * i) * K + kc);
            const uint32_t db = sbase +
                (uint32_t)(((2 * BM * SAo) + s * BN * SAo + (lr + 32 * i) * SAo + lc) * 4);
            cp_a16(db, Bg + (size_t)(32 * i) * K + kc);
        }
        asm volatile("cp.async.commit_group;" ::: "memory");
    };

    issue_tile(0, 0);

    const int KT = K / BK;
    for (int kt = 0; kt < KT; kt++) {
        const int s = kt & 1;
        if (kt + 1 < KT) {
            issue_tile(kt + 1, s ^ 1);
            asm volatile("cp.async.wait_group 1;" ::: "memory");
        } else {
            asm volatile("cp.async.wait_group 0;" ::: "memory");
        }
        __syncthreads();

        const float* Ab = sm + s * BM * SAo + wm * SAo;
        const float* Bb = sm + 2 * BM * SAo + s * BN * SAo + wn * SAo;
        #pragma unroll
        for (int ks = 0; ks < 4; ks++) {
            const int kk = ks * 8;
            uint32_t af[4][4];
            #pragma unroll
            for (int mi = 0; mi < 4; mi++) {
                const float* p = Ab + (mi * 16 + g) * SAo + kk + t;
                af[mi][0] = __float_as_uint(p[0]);
                af[mi][1] = __float_as_uint(p[8 * SAo]);
                af[mi][2] = __float_as_uint(p[4]);
                af[mi][3] = __float_as_uint(p[8 * SAo + 4]);
            }
            uint32_t bf[4][2];
            #pragma unroll
            for (int ni = 0; ni < 4; ni++) {
                const float* p = Bb + (ni * 8 + g) * SAo + kk + t;
                bf[ni][0] = __float_as_uint(p[0]);
                bf[ni][1] = __float_as_uint(p[4]);
            }
            #pragma unroll
            for (int mi = 0; mi < 4; mi++)
                #pragma unroll
                for (int ni = 0; ni < 4; ni++)
                    mma_tf32(acc[mi][ni], af[mi], bf[ni]);
        }
        __syncthreads();
    }

    // epilogue
    #pragma unroll
    for (int ni = 0; ni < 4; ni++) {
        const int cc = n0 + wn + ni * 8 + 2 * t;
        const float b0 = bias[cc];
        const float b1 = bias[cc + 1];
        #pragma unroll
        for (int mi = 0; mi < 4; mi++) {
            const int rr = m0 + wm + mi * 16 + g;
            float v0 = acc[mi][ni][0] + b0;
            float v1 = acc[mi][ni][1] + b1;
            float v2 = acc[mi][ni][2] + b0;
            float v3 = acc[mi][ni][3] + b1;
            if (GATE) {
                const float g0 = gate[rr];
                const float g1 = gate[rr + 8];
                v0 *= g0; v1 *= g0; v2 *= g1; v3 *= g1;
            }
            if (ROUND) {
                v0 = f2tf32(v0); v1 = f2tf32(v1);
                v2 = f2tf32(v2); v3 = f2tf32(v3);
            }
            *(float2*)(C + (size_t)rr * N + cc)       = make_float2(v0, v1);
            *(float2*)(C + (size_t)(rr + 8) * N + cc) = make_float2(v2, v3);
        }
    }
}

// ============================================================
// Flash attention: 128 threads (4 warps), each warp 32 q-rows.
// Q/K/V arrive pre-rounded tf32 -> no cvt in loaders.
// K/V double-buffered frag-layout smem; 1 __syncthreads per KV tile.
//   Kf/Vf: [nb(8)][ks(8)][lane(32)][2]  slot = (g^(ks>>2))*4 + (t^((nb^ks)&3))
//   Pf (per warp,mi): [ks(8)][lane(32)][4]  slot = g*4 + (t^((g>>1)&3))
// Output rounded to tf32 (feeds final GEMM).
// ============================================================
#define KF0_OFF   0
#define KF1_OFF   4096
#define VF0_OFF   8192
#define VF1_OFF   12288
#define PF_OFF    16384
#define SLR_OFF   24576
#define QS_OFF    8192
#define QS_STR    68
#define FATT_FLOATS 24704

__global__ __launch_bounds__(128, 2)
void flash_attn(const float* __restrict__ Q, const float* __restrict__ Kg,
                const float* __restrict__ V, const float* __restrict__ slrg,
                float* __restrict__ O)
{
    extern __shared__ float sm[];
    float* Pf  = sm + PF_OFF;
    float* Qs  = sm + QS_OFF;

    const int tid  = threadIdx.x;
    const int wid  = tid >> 5;
    const int lane = tid & 31;
    const int g    = lane >> 2;
    const int t    = lane & 3;
    const int q0   = blockIdx.x * 128;
    const int h    = blockIdx.y;
    const int b    = blockIdx.z;
    const int col0 = h * HDIM;
    const int wq   = wid * 32;

    // ---- stage Q tile (coalesced), extract frags to registers ----
    #pragma unroll
    for (int i = 0; i < 16; i++) {
        const int chunk = tid + 128 * i;
        const int row = chunk >> 4;
        const int c4  = (chunk & 15) * 4;
        float4 v = *(const float4*)(Q + (size_t)(b * NQL + q0 + row) * DIMC + col0 + c4);
        *(float4*)(Qs + row * QS_STR + c4) = v;
    }
    __syncthreads();

    uint32_t qf[2][8][4];
    #pragma unroll
    for (int mi = 0; mi < 2; mi++)
        #pragma unroll
        for (int ks = 0; ks < 8; ks++) {
            const float* p = Qs + (wq + mi * 16 + g) * QS_STR + ks * 8 + t;
            qf[mi][ks][0] = __float_as_uint(p[0]);
            qf[mi][ks][1] = __float_as_uint(p[8 * QS_STR]);
            qf[mi][ks][2] = __float_as_uint(p[4]);
            qf[mi][ks][3] = __float_as_uint(p[8 * QS_STR + 4]);
        }
    __syncthreads();   // Qs dead; smem free for KV buffers

    // loader geometry
    const int r0  = tid >> 4;          // 0..7
    const int c4  = (tid & 15) * 4;    // 0..60
    const int ksK = c4 >> 3;
    const int hkK = (c4 >> 2) & 1;
    const int nbV = c4 >> 3;
    const int g3b = c4 & 7;

    // prefetch tile 0
    float4 rk[8], rv[8];
    #pragma unroll
    for (int i = 0; i < 8; i++) {
        const int row = r0 + 8 * i;
        const size_t go = (size_t)(b * NKVL + row) * DIMC + col0 + c4;
        rk[i] = *(const float4*)(Kg + go);
        rv[i] = *(const float4*)(V  + go);
    }
    float slr_pre = (tid < 64) ? slrg[b * NKVL + tid] : 0.f;

    float mrow[2][2], lrow[2][2];
    #pragma unroll
    for (int mi = 0; mi < 2; mi++) { mrow[mi][0] = mrow[mi][1] = -1e30f; lrow[mi][0] = lrow[mi][1] = 0.f; }
    float oacc[2][8][4];
    #pragma unroll
    for (int mi = 0; mi < 2; mi++)
        #pragma unroll
        for (int nb = 0; nb < 8; nb++)
            #pragma unroll
            for (int c = 0; c < 4; c++) oacc[mi][nb][c] = 0.f;

    int buf = 0;
    for (int kt = 0; kt < NKVL / 64; kt++) {
        float* Kf = sm + (buf ? KF1_OFF : KF0_OFF);
        float* Vf = sm + (buf ? VF1_OFF : VF0_OFF);
        float* sl = sm + SLR_OFF + buf * 64;

        // ---- scatter prefetched tile into frag layouts (no cvt) ----
        #pragma unroll
        for (int i = 0; i < 8; i++) {
            const int row = r0 + 8 * i;
            const float kv[4] = {rk[i].x, rk[i].y, rk[i].z, rk[i].w};
            const float vv[4] = {rv[i].x, rv[i].y, rv[i].z, rv[i].w};
            {
                const int nb = row >> 3, g3 = row & 7;
                const int gs = g3 ^ (ksK >> 2);
                float* base = Kf + ((nb * 8 + ksK) * 32) * 2 + hkK;
                #pragma unroll
                for (int e = 0; e < 4; e++)
                    base[(gs * 4 + (e ^ ((nb ^ ksK) & 3))) * 2] = kv[e];
            }
            {
                const int ksV = row >> 3, tV = row & 3, hkV = (row >> 2) & 1;
                #pragma unroll
                for (int e = 0; e < 4; e++) {
                    const int gs = (g3b + e) ^ (ksV >> 2);
                    Vf[((nbV * 8 + ksV) * 32 + gs * 4 + (tV ^ ((nbV ^ ksV) & 3))) * 2 + hkV] = vv[e];
                }
            }
        }
        if (tid < 64) sl[tid] = slr_pre;
        __syncthreads();

        // ---- prefetch next tile K (hidden under QK) ----
        const int ktn = (kt + 1 < NKVL / 64) ? kt + 1 : kt;
        #pragma unroll
        for (int i = 0; i < 8; i++) {
            const int row = r0 + 8 * i;
            rk[i] = *(const float4*)(Kg + (size_t)(b * NKVL + ktn * 64 + row) * DIMC + col0 + c4);
        }
        if (tid < 64) slr_pre = slrg[b * NKVL + ktn * 64 + tid];

        // ---- per 16-row half: S = Q K^T, softmax, write P ----
        #pragma unroll
        for (int mi = 0; mi < 2; mi++) {
            float sacc[8][4];
            #pragma unroll
            for (int nb = 0; nb < 8; nb++)
                #pragma unroll
                for (int c = 0; c < 4; c++) sacc[nb][c] = 0.f;
            #pragma unroll
            for (int ks = 0; ks < 8; ks++) {
                #pragma unroll
                for (int nb = 0; nb < 8; nb++) {
                    const int slot = (g ^ (ks >> 2)) * 4 + (t ^ ((nb ^ ks) & 3));
                    float2 bv = *(const float2*)(Kf + ((nb * 8 + ks) * 32 + slot) * 2);
                    mma_tf32(sacc[nb], qf[mi][ks], (const uint32_t*)&bv);
                }
            }
            float mt0 = -1e30f, mt1 = -1e30f;
            #pragma unroll
            for (int nb = 0; nb < 8; nb++) {
                const int c = nb * 8 + 2 * t;
                const float l0 = sl[c], l1 = sl[c + 1];
                sacc[nb][0] = sacc[nb][0] * 0.125f + l0;
                sacc[nb][1] = sacc[nb][1] * 0.125f + l1;
                sacc[nb][2] = sacc[nb][2] * 0.125f + l0;
                sacc[nb][3] = sacc[nb][3] * 0.125f + l1;
                mt0 = fmaxf(mt0, fmaxf(sacc[nb][0], sacc[nb][1]));
                mt1 = fmaxf(mt1, fmaxf(sacc[nb][2], sacc[nb][3]));
            }
            mt0 = fmaxf(mt0, __shfl_xor_sync(0xffffffffu, mt0, 1));
            mt0 = fmaxf(mt0, __shfl_xor_sync(0xffffffffu, mt0, 2));
            mt1 = fmaxf(mt1, __shfl_xor_sync(0xffffffffu, mt1, 1));
            mt1 = fmaxf(mt1, __shfl_xor_sync(0xffffffffu, mt1, 2));
            const float mn0 = fmaxf(mrow[mi][0], mt0);
            const float mn1 = fmaxf(mrow[mi][1], mt1);

            const int t2 = (2 * t) & 3;
            const int hk = t >> 1;
            const int sg = (g >> 1) & 3;
            float* pw = Pf + ((wid * 2 + mi) * 8) * 128;
            float rs0 = 0.f, rs1 = 0.f;
            #pragma unroll
            for (int nb = 0; nb < 8; nb++) {
                const float p0 = __expf(sacc[nb][0] - mn0);
                const float p1 = __expf(sacc[nb][1] - mn0);
                const float p2 = __expf(sacc[nb][2] - mn1);
                const float p3 = __expf(sacc[nb][3] - mn1);
                rs0 += p0 + p1;
                rs1 += p2 + p3;
                float* base = pw + nb * 128;
                const int l0s = g * 4 + (t2 ^ sg);
                const int l1s = g * 4 + ((t2 + 1) ^ sg);
                *(float2*)(base + l0s * 4 + 2 * hk) = make_float2(f2tf32(p0), f2tf32(p2));
                *(float2*)(base + l1s * 4 + 2 * hk) = make_float2(f2tf32(p1), f2tf32(p3));
            }
            rs0 += __shfl_xor_sync(0xffffffffu, rs0, 1);
            rs0 += __shfl_xor_sync(0xffffffffu, rs0, 2);
            rs1 += __shfl_xor_sync(0xffffffffu, rs1, 1);
            rs1 += __shfl_xor_sync(0xffffffffu, rs1, 2);

            const float al0 = __expf(mrow[mi][0] - mn0);
            const float al1 = __expf(mrow[mi][1] - mn1);
            lrow[mi][0] = lrow[mi][0] * al0 + rs0;
            lrow[mi][1] = lrow[mi][1] * al1 + rs1;
            mrow[mi][0] = mn0; mrow[mi][1] = mn1;
            #pragma unroll
            for (int nb = 0; nb < 8; nb++) {
                oacc[mi][nb][0] *= al0; oacc[mi][nb][1] *= al0;
                oacc[mi][nb][2] *= al1; oacc[mi][nb][3] *= al1;
            }
        }
        __syncwarp();   // Pf is per-warp private

        // ---- prefetch next tile V (hidden under PV) ----
        #pragma unroll
        for (int i = 0; i < 8; i++) {
            const int row = r0 + 8 * i;
            rv[i] = *(const float4*)(V + (size_t)(b * NKVL + ktn * 64 + row) * DIMC + col0 + c4);
        }

        // ---- O += P V ----
        #pragma unroll
        for (int ks = 0; ks < 8; ks++) {
            const int pslot = g * 4 + (t ^ ((g >> 1) & 3));
            float4 a0 = *(const float4*)(Pf + ((wid * 2 + 0) * 8 + ks) * 128 + pslot * 4);
            float4 a1 = *(const float4*)(Pf + ((wid * 2 + 1) * 8 + ks) * 128 + pslot * 4);
            #pragma unroll
            for (int nb = 0; nb < 8; nb++) {
                const int slot = (g ^ (ks >> 2)) * 4 + (t ^ ((nb ^ ks) & 3));
                float2 bv = *(const float2*)(Vf + ((nb * 8 + ks) * 32 + slot) * 2);
                mma_tf32(oacc[0][nb], (const uint32_t*)&a0, (const uint32_t*)&bv);
                mma_tf32(oacc[1][nb], (const uint32_t*)&a1, (const uint32_t*)&bv);
            }
        }
        buf ^= 1;
    }

    // ---- epilogue (round output: feeds final GEMM) ----
    #pragma unroll
    for (int mi = 0; mi < 2; mi++) {
        const float il0 = 1.f / lrow[mi][0];
        const float il1 = 1.f / lrow[mi][1];
        const size_t orow = (size_t)(b * NQL + q0 + wq + mi * 16 + g);
        #pragma unroll
        for (int nb = 0; nb < 8; nb++) {
            const int c = col0 + nb * 8 + 2 * t;
            *(float2*)(O + orow * DIMC + c) =
                make_float2(f2tf32(oacc[mi][nb][0] * il0), f2tf32(oacc[mi][nb][1] * il0));
            *(float2*)(O + (orow + 8) * DIMC + c) =
                make_float2(f2tf32(oacc[mi][nb][2] * il1), f2tf32(oacc[mi][nb][3] * il1));
        }
    }
}

// ============================================================
// Launch
// ============================================================
extern "C" void kernel_launch(void* const* d_in, const int* in_sizes, int n_in,
                              void* d_out, int out_size)
{
    (void)in_sizes; (void)n_in; (void)out_size;
    const float* qf  = (const float*)d_in[0];
    const float* kvf = (const float*)d_in[1];
    const float* rel = (const float*)d_in[2];
    const float* Wq  = (const float*)d_in[3];
    const float* bq  = (const float*)d_in[4];
    const float* Wk  = (const float*)d_in[5];
    const float* bk  = (const float*)d_in[6];
    const float* Wv  = (const float*)d_in[7];
    const float* bv  = (const float*)d_in[8];
    const float* Wo  = (const float*)d_in[9];
    const float* bo  = (const float*)d_in[10];
    float* out = (float*)d_out;

    float *pq, *pk, *pv, *pao, *pxq, *pxkv, *pwq, *pwk, *pwv, *pwo, *pslr;
    cudaGetSymbolAddress((void**)&pq,   g_q);
    cudaGetSymbolAddress((void**)&pk,   g_k);
    cudaGetSymbolAddress((void**)&pv,   g_v);
    cudaGetSymbolAddress((void**)&pao,  g_ao);
    cudaGetSymbolAddress((void**)&pxq,  g_xq);
    cudaGetSymbolAddress((void**)&pxkv, g_xkv);
    cudaGetSymbolAddress((void**)&pwq,  g_wq);
    cudaGetSymbolAddress((void**)&pwk,  g_wk);
    cudaGetSymbolAddress((void**)&pwv,  g_wv);
    cudaGetSymbolAddress((void**)&pwo,  g_wo);
    cudaGetSymbolAddress((void**)&pslr, g_slr);

    const int gemm_smem  = (int)(2 * BM * SAo + 2 * BN * SAo) * 4;   // 73728 B
    const int flash_smem = FATT_FLOATS * 4;                          // 98816 B

    cudaFuncSetAttribute(gemm_nt<false, true>,
                         cudaFuncAttributeMaxDynamicSharedMemorySize, gemm_smem);
    cudaFuncSetAttribute(gemm_nt<true, true>,
                         cudaFuncAttributeMaxDynamicSharedMemorySize, gemm_smem);
    cudaFuncSetAttribute(gemm_nt<false, false>,
                         cudaFuncAttributeMaxDynamicSharedMemorySize, gemm_smem);
    cudaFuncSetAttribute(flash_attn,
                         cudaFuncAttributeMaxDynamicSharedMemorySize, flash_smem);

    // ---- prep: tf32 pre-rounding + log-reliability ----
    prep_slr<<<BATCH * NKVL / 256, 256>>>(rel, pslr);
    conv_tf32<<<(MROWS * DIMC) / 4 / 256, 256>>>(qf,  pxq);
    conv_tf32<<<(MROWS * DIMC) / 4 / 256, 256>>>(kvf, pxkv);
    conv_tf32<<<(DIMC * DIMC) / 4 / 256, 256>>>(Wq, pwq);
    conv_tf32<<<(DIMC * DIMC) / 4 / 256, 256>>>(Wk, pwk);
    conv_tf32<<<(DIMC * DIMC) / 4 / 256, 256>>>(Wv, pwv);
    conv_tf32<<<(DIMC * DIMC) / 4 / 256, 256>>>(Wo, pwo);

    dim3 gg(DIMC / BN, MROWS / BM);   // (8, 32)
    gemm_nt<false, true><<<gg, 256, gemm_smem>>>(pxq,  pwq, bq, nullptr, pq, MROWS, DIMC, DIMC);
    gemm_nt<true,  true><<<gg, 256, gemm_smem>>>(pxkv, pwk, bk, rel,     pk, MROWS, DIMC, DIMC);
    gemm_nt<true,  true><<<gg, 256, gemm_smem>>>(pxkv, pwv, bv, rel,     pv, MROWS, DIMC, DIMC);

    flash_attn<<<dim3(NQL / 128, HEADS, BATCH), 128, flash_smem>>>(pq, pk, pv, pslr, pao);

    gemm_nt<false, false><<<gg, 256, gemm_smem>>>(pao, pwo, bo, nullptr, out, MROWS, DIMC, DIMC);
}